// round 15
// baseline (speedup 1.0000x reference)
#include <cuda_runtime.h>
#include <cstdint>
#include <math.h>

#define B_  4096
#define P_  32
#define Z_  1000
#define ZE_ 64
#define PG_ 8
#define EH_ 256
#define L_  64
#define OH_ 128
#define T_  48
#define RP  36      // padded row stride for transposed 32-row tiles

typedef unsigned long long u64;

__device__ float g_predz[(size_t)B_ * T_ * L_];

// ---------------------------------------------------------------------------
// f32x2 helpers
// ---------------------------------------------------------------------------
__device__ __forceinline__ u64 pk2(float a, float b) {
    u64 r; asm("mov.b64 %0,{%1,%2};" : "=l"(r) : "f"(a), "f"(b)); return r;
}
__device__ __forceinline__ u64 f2(u64 a, u64 b, u64 c) {
    u64 d; asm("fma.rn.f32x2 %0,%1,%2,%3;" : "=l"(d) : "l"(a), "l"(b), "l"(c)); return d;
}
__device__ __forceinline__ u64 a2(u64 a, u64 b) {
    u64 d; asm("add.rn.f32x2 %0,%1,%2;" : "=l"(d) : "l"(a), "l"(b)); return d;
}
__device__ __forceinline__ float2 up2(u64 a) {
    float lo, hi; asm("mov.b64 {%0,%1},%2;" : "=f"(lo), "=f"(hi) : "l"(a));
    float2 v; v.x = lo; v.y = hi; return v;
}
__device__ __forceinline__ float fast_tanh(float x) {
    float e; asm("ex2.approx.f32 %0, %1;" : "=f"(e) : "f"(x * 2.885390081777927f));
    float r; asm("rcp.approx.f32 %0, %1;" : "=f"(r) : "f"(e + 1.0f));
    return 1.0f - 2.0f * r;
}
__device__ __forceinline__ u64 tanh2(u64 v) {
    float2 f = up2(v); return pk2(fast_tanh(f.x), fast_tanh(f.y));
}

// ---------------------------------------------------------------------------
// gemmT4: transposed-A gemm, thread = 4 rows x 2 cols, with one-chunk-ahead
// register prefetch of weights (hides ~250cyc L2 latency behind 8k of FMA).
// A_T: [K][RP]; acc[p][j]: row-pair p (rows r0+2p..), col c0+j.
// ---------------------------------------------------------------------------
template<int LDW, int K>
__device__ __forceinline__ void gemmT4(u64 acc[2][2], const float* __restrict__ sA_T, int r0,
                                       const float* __restrict__ W, int c0) {
    float2 wbuf[8];
#pragma unroll
    for (int kk = 0; kk < 8; kk++)
        wbuf[kk] = *(const float2*)(W + (size_t)kk * LDW + c0);
#pragma unroll 1
    for (int k0 = 0; k0 < K; k0 += 8) {
        float2 wnext[8];
        if (k0 + 8 < K) {
#pragma unroll
            for (int kk = 0; kk < 8; kk++)
                wnext[kk] = *(const float2*)(W + (size_t)(k0 + 8 + kk) * LDW + c0);
        }
#pragma unroll
        for (int kk = 0; kk < 8; kk++) {
            ulonglong2 a = *(const ulonglong2*)(sA_T + (k0 + kk) * RP + r0);
            u64 w0 = pk2(wbuf[kk].x, wbuf[kk].x);
            u64 w1 = pk2(wbuf[kk].y, wbuf[kk].y);
            acc[0][0] = f2(a.x, w0, acc[0][0]); acc[0][1] = f2(a.x, w1, acc[0][1]);
            acc[1][0] = f2(a.y, w0, acc[1][0]); acc[1][1] = f2(a.y, w1, acc[1][1]);
        }
#pragma unroll
        for (int kk = 0; kk < 8; kk++) wbuf[kk] = wnext[kk];
    }
}

// ---------------------------------------------------------------------------
// Encoder: unchanged (≈70us).
// ---------------------------------------------------------------------------
__global__ void __launch_bounds__(256) enc_kernel(
    const float* __restrict__ person, const int* __restrict__ home_id,
    const int* __restrict__ work_id, const float* __restrict__ purpose,
    const float* __restrict__ eps, const float* __restrict__ ztab,
    const float* __restrict__ W1, const float* __restrict__ b1,
    const float* __restrict__ W2, const float* __restrict__ b2,
    float* __restrict__ out_mu, float* __restrict__ out_lv)
{
    __shared__ float EI[16 * 168];
    __shared__ float H[16 * 256];
    __shared__ float LAT[16 * 128];
    const int tid = threadIdx.x;
    const int w = tid >> 5, lane = tid & 31;
    const int b0 = blockIdx.x * 16;

    for (int idx = tid; idx < 16 * 168; idx += 256) {
        int r = idx / 168, j = idx % 168, b = b0 + r;
        float v;
        if (j < 32)       v = person[b * 32 + j];
        else if (j < 96)  v = ztab[(size_t)home_id[b] * 64 + (j - 32)];
        else if (j < 160) v = ztab[(size_t)work_id[b] * 64 + (j - 96)];
        else              v = purpose[b * 8 + (j - 160)];
        EI[idx] = v;
    }
    __syncthreads();

    { // GEMM1 + relu
        int c0 = w * 32 + (lane & 7) * 4;
        int r0 = (lane >> 3) * 4;
        u64 acc[4][2];
        u64 i0 = pk2(b1[c0], b1[c0 + 1]), i1 = pk2(b1[c0 + 2], b1[c0 + 3]);
#pragma unroll
        for (int r = 0; r < 4; r++) { acc[r][0] = i0; acc[r][1] = i1; }
#pragma unroll 4
        for (int k = 0; k < 168; k += 2) {
            float2 a[4];
#pragma unroll
            for (int r = 0; r < 4; r++) a[r] = *(const float2*)(EI + (r0 + r) * 168 + k);
            ulonglong2 w0 = *(const ulonglong2*)(W1 + (size_t)k * 256 + c0);
            ulonglong2 w1 = *(const ulonglong2*)(W1 + (size_t)(k + 1) * 256 + c0);
#pragma unroll
            for (int r = 0; r < 4; r++) {
                u64 x = pk2(a[r].x, a[r].x);
                acc[r][0] = f2(x, w0.x, acc[r][0]); acc[r][1] = f2(x, w0.y, acc[r][1]);
                x = pk2(a[r].y, a[r].y);
                acc[r][0] = f2(x, w1.x, acc[r][0]); acc[r][1] = f2(x, w1.y, acc[r][1]);
            }
        }
#pragma unroll
        for (int r = 0; r < 4; r++) {
            float2 v0 = up2(acc[r][0]), v1 = up2(acc[r][1]);
            float4 o;
            o.x = fmaxf(v0.x, 0.f); o.y = fmaxf(v0.y, 0.f);
            o.z = fmaxf(v1.x, 0.f); o.w = fmaxf(v1.y, 0.f);
            *(float4*)&H[(r0 + r) * 256 + c0] = o;
        }
    }
    __syncthreads();

    { // GEMM2
        int c0 = w * 16 + (lane & 3) * 4;
        int r0 = (lane >> 2) * 2;
        u64 acc[2][2];
        u64 i0 = pk2(b2[c0], b2[c0 + 1]), i1 = pk2(b2[c0 + 2], b2[c0 + 3]);
#pragma unroll
        for (int r = 0; r < 2; r++) { acc[r][0] = i0; acc[r][1] = i1; }
#pragma unroll 4
        for (int k = 0; k < 256; k += 2) {
            float2 a[2];
#pragma unroll
            for (int r = 0; r < 2; r++) a[r] = *(const float2*)(H + (r0 + r) * 256 + k);
            ulonglong2 w0 = *(const ulonglong2*)(W2 + (size_t)k * 128 + c0);
            ulonglong2 w1 = *(const ulonglong2*)(W2 + (size_t)(k + 1) * 128 + c0);
#pragma unroll
            for (int r = 0; r < 2; r++) {
                u64 x = pk2(a[r].x, a[r].x);
                acc[r][0] = f2(x, w0.x, acc[r][0]); acc[r][1] = f2(x, w0.y, acc[r][1]);
                x = pk2(a[r].y, a[r].y);
                acc[r][0] = f2(x, w1.x, acc[r][0]); acc[r][1] = f2(x, w1.y, acc[r][1]);
            }
        }
#pragma unroll
        for (int r = 0; r < 2; r++) {
            float2 v0 = up2(acc[r][0]), v1 = up2(acc[r][1]);
            float4 o; o.x = v0.x; o.y = v0.y; o.z = v1.x; o.w = v1.y;
            *(float4*)&LAT[(r0 + r) * 128 + c0] = o;
        }
    }
    __syncthreads();

    for (int idx = tid; idx < 16 * 64; idx += 256) {
        int r = idx >> 6, c = idx & 63, b = b0 + r;
        float mu = LAT[r * 128 + c];
        float lv = LAT[r * 128 + 64 + c];
        float z0 = mu + eps[(size_t)b * 64 + c] * expf(0.5f * lv);
        out_mu[(size_t)b * 64 + c] = mu;
        out_lv[(size_t)b * 64 + c] = lv;
        g_predz[(size_t)b * (T_ * L_) + c] = z0;
    }
}

// ---------------------------------------------------------------------------
// ODE dynamics, 512 threads (16 warps). Thread = 4 rows x 2 cols.
// sX: [160][RP], zin/sF: [64][RP], sH/sH2: [128][RP]
// ---------------------------------------------------------------------------
__device__ __forceinline__ void ode_f(
    int tid, float t,
    const float* __restrict__ sX, const float* __restrict__ zin,
    float* __restrict__ sH, float* __restrict__ sH2, float* __restrict__ sF,
    const float* __restrict__ sB,
    const float* __restrict__ Wi,
    const float* __restrict__ W11, const float* __restrict__ W12,
    const float* __restrict__ W21, const float* __restrict__ W22,
    const float* __restrict__ Wo)
{
    const int w = tid >> 5, lane = tid & 31;
    const int cg = lane & 3, rg = lane >> 2;
    const int c0 = w * 8 + cg * 2;    // 2 cols in [0,128)
    const int r0 = rg * 4;            // 4 rows in [0,32)

    { // layer 0: tanh(x @ Wi + bi), t-term folded into bias
        u64 acc[2][2];
        float2 wt = *(const float2*)(Wi + 64 * 128 + c0);
        float bv0 = sB[c0] + t * wt.x, bv1 = sB[c0 + 1] + t * wt.y;
        acc[0][0] = acc[1][0] = pk2(bv0, bv0);
        acc[0][1] = acc[1][1] = pk2(bv1, bv1);
        gemmT4<128, 64>(acc, zin, r0, Wi, c0);               // z rows 0..63
        gemmT4<128, 160>(acc, sX, r0, Wi + 65 * 128, c0);    // static rows 65..224
#pragma unroll
        for (int j = 0; j < 2; j++) {
            ulonglong2 v;
            v.x = tanh2(acc[0][j]); v.y = tanh2(acc[1][j]);
            *(ulonglong2*)(sH + (c0 + j) * RP + r0) = v;
        }
    }
    __syncthreads();

    const float* rW1[2] = { W11, W21 };
    const float* rW2[2] = { W12, W22 };
    const int ob1[2] = { 128, 384 };
    const int ob2[2] = { 256, 512 };

#pragma unroll 1
    for (int rb = 0; rb < 2; rb++) {
        { // inner: tanh(h @ W1 + b1) -> sH2
            u64 acc[2][2];
            const float* bb = sB + ob1[rb];
            acc[0][0] = acc[1][0] = pk2(bb[c0], bb[c0]);
            acc[0][1] = acc[1][1] = pk2(bb[c0 + 1], bb[c0 + 1]);
            gemmT4<128, 128>(acc, sH, r0, rW1[rb], c0);
#pragma unroll
            for (int j = 0; j < 2; j++) {
                ulonglong2 v;
                v.x = tanh2(acc[0][j]); v.y = tanh2(acc[1][j]);
                *(ulonglong2*)(sH2 + (c0 + j) * RP + r0) = v;
            }
        }
        __syncthreads();
        { // outer: h = tanh(h + sH2 @ W2 + b2) -> sH (thread owns its tile)
            u64 acc[2][2];
            const float* bb = sB + ob2[rb];
            acc[0][0] = acc[1][0] = pk2(bb[c0], bb[c0]);
            acc[0][1] = acc[1][1] = pk2(bb[c0 + 1], bb[c0 + 1]);
            gemmT4<128, 128>(acc, sH2, r0, rW2[rb], c0);
#pragma unroll
            for (int j = 0; j < 2; j++) {
                ulonglong2 p = *(const ulonglong2*)(sH + (c0 + j) * RP + r0);
                ulonglong2 v;
                v.x = tanh2(a2(acc[0][j], p.x));
                v.y = tanh2(a2(acc[1][j], p.y));
                *(ulonglong2*)(sH + (c0 + j) * RP + r0) = v;
            }
        }
        __syncthreads();
    }

    { // output: sF = h @ Wo + bo  (32x64); thread = 4 rows x 1 col
        int c0o = w * 4 + cg;
        u64 acc1[2];
        acc1[0] = acc1[1] = pk2(sB[640 + c0o], sB[640 + c0o]);
        float wbuf[8];
#pragma unroll
        for (int kk = 0; kk < 8; kk++) wbuf[kk] = Wo[(size_t)kk * 64 + c0o];
#pragma unroll 1
        for (int k0 = 0; k0 < 128; k0 += 8) {
            float wnext[8];
            if (k0 + 8 < 128) {
#pragma unroll
                for (int kk = 0; kk < 8; kk++)
                    wnext[kk] = Wo[(size_t)(k0 + 8 + kk) * 64 + c0o];
            }
#pragma unroll
            for (int kk = 0; kk < 8; kk++) {
                ulonglong2 a = *(const ulonglong2*)(sH + (k0 + kk) * RP + r0);
                u64 wd = pk2(wbuf[kk], wbuf[kk]);
                acc1[0] = f2(a.x, wd, acc1[0]);
                acc1[1] = f2(a.y, wd, acc1[1]);
            }
#pragma unroll
            for (int kk = 0; kk < 8; kk++) wbuf[kk] = wnext[kk];
        }
        ulonglong2 v; v.x = acc1[0]; v.y = acc1[1];
        *(ulonglong2*)(sF + c0o * RP + r0) = v;
    }
    __syncthreads();
}

// ---------------------------------------------------------------------------
// Persistent RK4 integrator: one block = 32 batch rows, 512 threads, 47 steps.
// ---------------------------------------------------------------------------
__global__ void __launch_bounds__(512) ode_kernel(
    const float* __restrict__ person, const int* __restrict__ home_id,
    const int* __restrict__ work_id, const float* __restrict__ ztab,
    const float* __restrict__ times,
    const float* __restrict__ Wi, const float* __restrict__ bi,
    const float* __restrict__ W11, const float* __restrict__ b11,
    const float* __restrict__ W12, const float* __restrict__ b12,
    const float* __restrict__ W21, const float* __restrict__ b21,
    const float* __restrict__ W22, const float* __restrict__ b22,
    const float* __restrict__ Wo, const float* __restrict__ bo)
{
    extern __shared__ float sm[];
    float* sX  = sm;             // 160*RP = 5760
    float* sZ  = sX + 5760;      // 64*RP = 2304
    float* sZt = sZ + 2304;      // 2304
    float* sKs = sZt + 2304;     // 2304
    float* sH  = sKs + 2304;     // 128*RP = 4608
    float* sH2 = sH + 4608;      // 4608
    float* sF  = sH2 + 4608;     // 2304
    float* sB  = sF + 2304;      // 704
    float* sT  = sB + 704;       // 48

    const int tid = threadIdx.x;
    const int b0 = blockIdx.x * 32;

    for (int idx = tid; idx < 32 * 160; idx += 512) {
        int r = idx / 160, j = idx % 160, b = b0 + r;
        float v;
        if (j < 32)      v = person[b * 32 + j];
        else if (j < 96) v = ztab[(size_t)work_id[b] * 64 + (j - 32)];
        else             v = ztab[(size_t)home_id[b] * 64 + (j - 96)];
        sX[j * RP + r] = v;
    }
    for (int idx = tid; idx < 2048; idx += 512) {
        int c = idx & 63, r = idx >> 6;
        sZ[c * RP + r] = g_predz[(size_t)(b0 + r) * (T_ * L_) + c];
    }
    if (tid < 128) {
        sB[tid]       = bi[tid];
        sB[128 + tid] = b11[tid];
        sB[256 + tid] = b12[tid];
        sB[384 + tid] = b21[tid];
        sB[512 + tid] = b22[tid];
        if (tid < 64) sB[640 + tid] = bo[tid];
        if (tid < 48) sT[tid] = times[tid];
    }
    __syncthreads();

    for (int s = 0; s < T_ - 1; s++) {
        float t0 = sT[s], t1 = sT[s + 1];
        float dt = t1 - t0;

        ode_f(tid, t0, sX, sZ, sH, sH2, sF, sB, Wi, W11, W12, W21, W22, Wo);
        for (int idx = tid; idx < 2048; idx += 512) {
            int c = idx & 63, r = idx >> 6; int off = c * RP + r;
            float k1 = sF[off];
            sKs[off] = k1;
            sZt[off] = sZ[off] + 0.5f * dt * k1;
        }
        __syncthreads();

        ode_f(tid, t0 + 0.5f * dt, sX, sZt, sH, sH2, sF, sB, Wi, W11, W12, W21, W22, Wo);
        for (int idx = tid; idx < 2048; idx += 512) {
            int c = idx & 63, r = idx >> 6; int off = c * RP + r;
            float k2 = sF[off];
            sKs[off] += 2.0f * k2;
            sZt[off] = sZ[off] + 0.5f * dt * k2;
        }
        __syncthreads();

        ode_f(tid, t0 + 0.5f * dt, sX, sZt, sH, sH2, sF, sB, Wi, W11, W12, W21, W22, Wo);
        for (int idx = tid; idx < 2048; idx += 512) {
            int c = idx & 63, r = idx >> 6; int off = c * RP + r;
            float k3 = sF[off];
            sKs[off] += 2.0f * k3;
            sZt[off] = sZ[off] + dt * k3;
        }
        __syncthreads();

        ode_f(tid, t1, sX, sZt, sH, sH2, sF, sB, Wi, W11, W12, W21, W22, Wo);
        for (int idx = tid; idx < 2048; idx += 512) {
            int c = idx & 63, r = idx >> 6; int off = c * RP + r;
            float zn = sZ[off] + (dt * (1.0f / 6.0f)) * (sKs[off] + sF[off]);
            sZ[off] = zn;
            g_predz[(size_t)(b0 + r) * (T_ * L_) + (size_t)(s + 1) * L_ + c] = zn;
        }
        __syncthreads();
    }
}

// ---------------------------------------------------------------------------
// Decoder: unchanged from R12 (64-row x 128-col tiles, transposed PZ).
// ---------------------------------------------------------------------------
#define RPD 68   // 64 rows + 4 pad
__global__ void __launch_bounds__(256) dec_kernel(
    const float* __restrict__ dW, const float* __restrict__ db,
    float* __restrict__ out)
{
    __shared__ float PZ[64 * RPD];    // [64 cols][RPD rows]
    const int tid = threadIdx.x;
    const int w = tid >> 5, lane = tid & 31;
    const int ct = blockIdx.x;                 // 0..7
    const size_t row0 = (size_t)blockIdx.y * 64;

    for (int idx = tid; idx < 4096; idx += 256) {
        int c = idx & 63, r = idx >> 6;
        PZ[c * RPD + r] = g_predz[row0 * 64 + idx];
    }
    __syncthreads();

    const int cg = lane & 3, rg = lane >> 2;   // 4 cgs x 8 rgs
    const int c0 = ct * 128 + w * 16 + cg * 4;
    const int r0 = rg * 8;
    if (c0 >= Z_) return;

    u64 acc[4][4];
#pragma unroll
    for (int j = 0; j < 4; j++) {
        u64 ib = pk2(db[c0 + j], db[c0 + j]);
#pragma unroll
        for (int p = 0; p < 4; p++) acc[p][j] = ib;
    }
#pragma unroll 4
    for (int k = 0; k < 64; k++) {
        ulonglong2 a01 = *(const ulonglong2*)(PZ + k * RPD + r0);
        ulonglong2 a23 = *(const ulonglong2*)(PZ + k * RPD + r0 + 4);
        float4 wv = *(const float4*)(dW + (size_t)k * Z_ + c0);
        u64 wd[4];
        wd[0] = pk2(wv.x, wv.x); wd[1] = pk2(wv.y, wv.y);
        wd[2] = pk2(wv.z, wv.z); wd[3] = pk2(wv.w, wv.w);
        u64 ap[4] = { a01.x, a01.y, a23.x, a23.y };
#pragma unroll
        for (int p = 0; p < 4; p++)
#pragma unroll
            for (int j = 0; j < 4; j++)
                acc[p][j] = f2(ap[p], wd[j], acc[p][j]);
    }
#pragma unroll
    for (int p = 0; p < 4; p++) {
        float2 e0 = up2(acc[p][0]), e1 = up2(acc[p][1]);
        float2 e2 = up2(acc[p][2]), e3 = up2(acc[p][3]);
        float4 lo; lo.x = e0.x; lo.y = e1.x; lo.z = e2.x; lo.w = e3.x;
        float4 hi; hi.x = e0.y; hi.y = e1.y; hi.z = e2.y; hi.w = e3.y;
        *(float4*)&out[(row0 + r0 + 2 * p)     * Z_ + c0] = lo;
        *(float4*)&out[(row0 + r0 + 2 * p + 1) * Z_ + c0] = hi;
    }
}

// ---------------------------------------------------------------------------
extern "C" void kernel_launch(void* const* d_in, const int* in_sizes, int n_in,
                              void* d_out, int out_size)
{
    const float* person  = (const float*)d_in[0];
    const int*   home_id = (const int*)  d_in[1];
    const int*   work_id = (const int*)  d_in[2];
    const float* purpose = (const float*)d_in[3];
    const float* times   = (const float*)d_in[4];
    const float* eps     = (const float*)d_in[5];
    const float* ztab    = (const float*)d_in[6];
    const float* eW1     = (const float*)d_in[7];
    const float* eb1     = (const float*)d_in[8];
    const float* eW2     = (const float*)d_in[9];
    const float* eb2     = (const float*)d_in[10];
    const float* dW      = (const float*)d_in[11];
    const float* db      = (const float*)d_in[12];
    const float* Wi      = (const float*)d_in[13];
    const float* bi      = (const float*)d_in[14];
    const float* W11     = (const float*)d_in[15];
    const float* b11     = (const float*)d_in[16];
    const float* W12     = (const float*)d_in[17];
    const float* b12     = (const float*)d_in[18];
    const float* W21     = (const float*)d_in[19];
    const float* b21     = (const float*)d_in[20];
    const float* W22     = (const float*)d_in[21];
    const float* b22     = (const float*)d_in[22];
    const float* Wo      = (const float*)d_in[23];
    const float* bo      = (const float*)d_in[24];

    float* out_logits = (float*)d_out;                          // [B, T, Z]
    float* out_mu     = out_logits + (size_t)B_ * T_ * Z_;      // [B, L]
    float* out_lv     = out_mu + (size_t)B_ * L_;               // [B, L]

    enc_kernel<<<B_ / 16, 256>>>(person, home_id, work_id, purpose, eps, ztab,
                                 eW1, eb1, eW2, eb2, out_mu, out_lv);

    const int ODE_SMEM = (5760 + 2304 * 3 + 4608 * 2 + 2304 + 704 + 48) * 4; // 99776 B
    cudaFuncSetAttribute(ode_kernel, cudaFuncAttributeMaxDynamicSharedMemorySize, ODE_SMEM);
    ode_kernel<<<B_ / 32, 512, ODE_SMEM>>>(person, home_id, work_id, ztab, times,
                                           Wi, bi, W11, b11, W12, b12,
                                           W21, b21, W22, b22, Wo, bo);

    dim3 dgrid(8, (B_ * T_) / 64);
    dec_kernel<<<dgrid, 256>>>(dW, db, out_logits);
}

// round 16
// speedup vs baseline: 2.7164x; 2.7164x over previous
#include <cuda_runtime.h>
#include <cstdint>
#include <math.h>

#define B_  4096
#define P_  32
#define Z_  1000
#define ZE_ 64
#define PG_ 8
#define EH_ 256
#define L_  64
#define OH_ 128
#define T_  48
#define RP  36      // padded row stride for transposed 32-row tiles

typedef unsigned long long u64;

__device__ float g_predz[(size_t)B_ * T_ * L_];

// ---------------------------------------------------------------------------
// f32x2 helpers
// ---------------------------------------------------------------------------
__device__ __forceinline__ u64 pk2(float a, float b) {
    u64 r; asm("mov.b64 %0,{%1,%2};" : "=l"(r) : "f"(a), "f"(b)); return r;
}
__device__ __forceinline__ u64 f2(u64 a, u64 b, u64 c) {
    u64 d; asm("fma.rn.f32x2 %0,%1,%2,%3;" : "=l"(d) : "l"(a), "l"(b), "l"(c)); return d;
}
__device__ __forceinline__ u64 a2(u64 a, u64 b) {
    u64 d; asm("add.rn.f32x2 %0,%1,%2;" : "=l"(d) : "l"(a), "l"(b)); return d;
}
__device__ __forceinline__ float2 up2(u64 a) {
    float lo, hi; asm("mov.b64 {%0,%1},%2;" : "=f"(lo), "=f"(hi) : "l"(a));
    float2 v; v.x = lo; v.y = hi; return v;
}
__device__ __forceinline__ float fast_tanh(float x) {
    float e; asm("ex2.approx.f32 %0, %1;" : "=f"(e) : "f"(x * 2.885390081777927f));
    float r; asm("rcp.approx.f32 %0, %1;" : "=f"(r) : "f"(e + 1.0f));
    return 1.0f - 2.0f * r;
}
__device__ __forceinline__ u64 tanh2(u64 v) {
    float2 f = up2(v); return pk2(fast_tanh(f.x), fast_tanh(f.y));
}

// ---------------------------------------------------------------------------
// gemmT4: transposed-A gemm, thread = 4 rows x 2 cols. Plain unroll-8 loop —
// no manual prefetch buffers (ptxas pipelines loads; 4 warps/SMSP hide L2).
// A_T: [K][RP]; acc[p][j]: row-pair p (rows r0+2p, r0+2p+1), col c0+j.
// ---------------------------------------------------------------------------
template<int LDW>
__device__ __forceinline__ void gemmT4(u64 acc[2][2], const float* __restrict__ sA_T, int r0,
                                       const float* __restrict__ W, int c0, int K) {
#pragma unroll 8
    for (int k = 0; k < K; k++) {
        ulonglong2 a = *(const ulonglong2*)(sA_T + k * RP + r0);
        float2 wv = *(const float2*)(W + (size_t)k * LDW + c0);
        u64 w0 = pk2(wv.x, wv.x), w1 = pk2(wv.y, wv.y);
        acc[0][0] = f2(a.x, w0, acc[0][0]); acc[0][1] = f2(a.x, w1, acc[0][1]);
        acc[1][0] = f2(a.y, w0, acc[1][0]); acc[1][1] = f2(a.y, w1, acc[1][1]);
    }
}

// ---------------------------------------------------------------------------
// Encoder: unchanged (≈70us).
// ---------------------------------------------------------------------------
__global__ void __launch_bounds__(256) enc_kernel(
    const float* __restrict__ person, const int* __restrict__ home_id,
    const int* __restrict__ work_id, const float* __restrict__ purpose,
    const float* __restrict__ eps, const float* __restrict__ ztab,
    const float* __restrict__ W1, const float* __restrict__ b1,
    const float* __restrict__ W2, const float* __restrict__ b2,
    float* __restrict__ out_mu, float* __restrict__ out_lv)
{
    __shared__ float EI[16 * 168];
    __shared__ float H[16 * 256];
    __shared__ float LAT[16 * 128];
    const int tid = threadIdx.x;
    const int w = tid >> 5, lane = tid & 31;
    const int b0 = blockIdx.x * 16;

    for (int idx = tid; idx < 16 * 168; idx += 256) {
        int r = idx / 168, j = idx % 168, b = b0 + r;
        float v;
        if (j < 32)       v = person[b * 32 + j];
        else if (j < 96)  v = ztab[(size_t)home_id[b] * 64 + (j - 32)];
        else if (j < 160) v = ztab[(size_t)work_id[b] * 64 + (j - 96)];
        else              v = purpose[b * 8 + (j - 160)];
        EI[idx] = v;
    }
    __syncthreads();

    { // GEMM1 + relu
        int c0 = w * 32 + (lane & 7) * 4;
        int r0 = (lane >> 3) * 4;
        u64 acc[4][2];
        u64 i0 = pk2(b1[c0], b1[c0 + 1]), i1 = pk2(b1[c0 + 2], b1[c0 + 3]);
#pragma unroll
        for (int r = 0; r < 4; r++) { acc[r][0] = i0; acc[r][1] = i1; }
#pragma unroll 4
        for (int k = 0; k < 168; k += 2) {
            float2 a[4];
#pragma unroll
            for (int r = 0; r < 4; r++) a[r] = *(const float2*)(EI + (r0 + r) * 168 + k);
            ulonglong2 w0 = *(const ulonglong2*)(W1 + (size_t)k * 256 + c0);
            ulonglong2 w1 = *(const ulonglong2*)(W1 + (size_t)(k + 1) * 256 + c0);
#pragma unroll
            for (int r = 0; r < 4; r++) {
                u64 x = pk2(a[r].x, a[r].x);
                acc[r][0] = f2(x, w0.x, acc[r][0]); acc[r][1] = f2(x, w0.y, acc[r][1]);
                x = pk2(a[r].y, a[r].y);
                acc[r][0] = f2(x, w1.x, acc[r][0]); acc[r][1] = f2(x, w1.y, acc[r][1]);
            }
        }
#pragma unroll
        for (int r = 0; r < 4; r++) {
            float2 v0 = up2(acc[r][0]), v1 = up2(acc[r][1]);
            float4 o;
            o.x = fmaxf(v0.x, 0.f); o.y = fmaxf(v0.y, 0.f);
            o.z = fmaxf(v1.x, 0.f); o.w = fmaxf(v1.y, 0.f);
            *(float4*)&H[(r0 + r) * 256 + c0] = o;
        }
    }
    __syncthreads();

    { // GEMM2
        int c0 = w * 16 + (lane & 3) * 4;
        int r0 = (lane >> 2) * 2;
        u64 acc[2][2];
        u64 i0 = pk2(b2[c0], b2[c0 + 1]), i1 = pk2(b2[c0 + 2], b2[c0 + 3]);
#pragma unroll
        for (int r = 0; r < 2; r++) { acc[r][0] = i0; acc[r][1] = i1; }
#pragma unroll 4
        for (int k = 0; k < 256; k += 2) {
            float2 a[2];
#pragma unroll
            for (int r = 0; r < 2; r++) a[r] = *(const float2*)(H + (r0 + r) * 256 + k);
            ulonglong2 w0 = *(const ulonglong2*)(W2 + (size_t)k * 128 + c0);
            ulonglong2 w1 = *(const ulonglong2*)(W2 + (size_t)(k + 1) * 128 + c0);
#pragma unroll
            for (int r = 0; r < 2; r++) {
                u64 x = pk2(a[r].x, a[r].x);
                acc[r][0] = f2(x, w0.x, acc[r][0]); acc[r][1] = f2(x, w0.y, acc[r][1]);
                x = pk2(a[r].y, a[r].y);
                acc[r][0] = f2(x, w1.x, acc[r][0]); acc[r][1] = f2(x, w1.y, acc[r][1]);
            }
        }
#pragma unroll
        for (int r = 0; r < 2; r++) {
            float2 v0 = up2(acc[r][0]), v1 = up2(acc[r][1]);
            float4 o; o.x = v0.x; o.y = v0.y; o.z = v1.x; o.w = v1.y;
            *(float4*)&LAT[(r0 + r) * 128 + c0] = o;
        }
    }
    __syncthreads();

    for (int idx = tid; idx < 16 * 64; idx += 256) {
        int r = idx >> 6, c = idx & 63, b = b0 + r;
        float mu = LAT[r * 128 + c];
        float lv = LAT[r * 128 + 64 + c];
        float z0 = mu + eps[(size_t)b * 64 + c] * expf(0.5f * lv);
        out_mu[(size_t)b * 64 + c] = mu;
        out_lv[(size_t)b * 64 + c] = lv;
        g_predz[(size_t)b * (T_ * L_) + c] = z0;
    }
}

// ---------------------------------------------------------------------------
// ODE dynamics, 512 threads (16 warps). Thread = 4 rows x 2 cols.
// sX: [160][RP], zin/sF: [64][RP], sH/sH2: [128][RP]
// ---------------------------------------------------------------------------
__device__ __forceinline__ void ode_f(
    int tid, float t,
    const float* __restrict__ sX, const float* __restrict__ zin,
    float* __restrict__ sH, float* __restrict__ sH2, float* __restrict__ sF,
    const float* __restrict__ sB,
    const float* __restrict__ Wi,
    const float* __restrict__ W11, const float* __restrict__ W12,
    const float* __restrict__ W21, const float* __restrict__ W22,
    const float* __restrict__ Wo)
{
    const int w = tid >> 5, lane = tid & 31;
    const int cg = lane & 3, rg = lane >> 2;
    const int c0 = w * 8 + cg * 2;    // 2 cols in [0,128)
    const int r0 = rg * 4;            // 4 rows in [0,32)

    { // layer 0: tanh(x @ Wi + bi), t-term folded into bias
        u64 acc[2][2];
        float2 wt = *(const float2*)(Wi + 64 * 128 + c0);
        float bv0 = sB[c0] + t * wt.x, bv1 = sB[c0 + 1] + t * wt.y;
        acc[0][0] = acc[1][0] = pk2(bv0, bv0);
        acc[0][1] = acc[1][1] = pk2(bv1, bv1);
        gemmT4<128>(acc, zin, r0, Wi, c0, 64);               // z rows 0..63
        gemmT4<128>(acc, sX, r0, Wi + 65 * 128, c0, 160);    // static rows 65..224
#pragma unroll
        for (int j = 0; j < 2; j++) {
            ulonglong2 v;
            v.x = tanh2(acc[0][j]); v.y = tanh2(acc[1][j]);
            *(ulonglong2*)(sH + (c0 + j) * RP + r0) = v;
        }
    }
    __syncthreads();

    const float* rW1[2] = { W11, W21 };
    const float* rW2[2] = { W12, W22 };
    const int ob1[2] = { 128, 384 };
    const int ob2[2] = { 256, 512 };

#pragma unroll 1
    for (int rb = 0; rb < 2; rb++) {
        { // inner: tanh(h @ W1 + b1) -> sH2
            u64 acc[2][2];
            const float* bb = sB + ob1[rb];
            acc[0][0] = acc[1][0] = pk2(bb[c0], bb[c0]);
            acc[0][1] = acc[1][1] = pk2(bb[c0 + 1], bb[c0 + 1]);
            gemmT4<128>(acc, sH, r0, rW1[rb], c0, 128);
#pragma unroll
            for (int j = 0; j < 2; j++) {
                ulonglong2 v;
                v.x = tanh2(acc[0][j]); v.y = tanh2(acc[1][j]);
                *(ulonglong2*)(sH2 + (c0 + j) * RP + r0) = v;
            }
        }
        __syncthreads();
        { // outer: h = tanh(h + sH2 @ W2 + b2) -> sH (thread owns its tile)
            u64 acc[2][2];
            const float* bb = sB + ob2[rb];
            acc[0][0] = acc[1][0] = pk2(bb[c0], bb[c0]);
            acc[0][1] = acc[1][1] = pk2(bb[c0 + 1], bb[c0 + 1]);
            gemmT4<128>(acc, sH2, r0, rW2[rb], c0, 128);
#pragma unroll
            for (int j = 0; j < 2; j++) {
                ulonglong2 p = *(const ulonglong2*)(sH + (c0 + j) * RP + r0);
                ulonglong2 v;
                v.x = tanh2(a2(acc[0][j], p.x));
                v.y = tanh2(a2(acc[1][j], p.y));
                *(ulonglong2*)(sH + (c0 + j) * RP + r0) = v;
            }
        }
        __syncthreads();
    }

    { // output: sF = h @ Wo + bo  (32x64); thread = 4 rows x 1 col
        int c0o = w * 4 + cg;
        u64 acc1[2];
        acc1[0] = acc1[1] = pk2(sB[640 + c0o], sB[640 + c0o]);
#pragma unroll 8
        for (int k = 0; k < 128; k++) {
            ulonglong2 a = *(const ulonglong2*)(sH + k * RP + r0);
            float wv = Wo[(size_t)k * 64 + c0o];
            u64 wd = pk2(wv, wv);
            acc1[0] = f2(a.x, wd, acc1[0]);
            acc1[1] = f2(a.y, wd, acc1[1]);
        }
        ulonglong2 v; v.x = acc1[0]; v.y = acc1[1];
        *(ulonglong2*)(sF + c0o * RP + r0) = v;
    }
    __syncthreads();
}

// ---------------------------------------------------------------------------
// Persistent RK4 integrator: one block = 32 batch rows, 512 threads, 47 steps.
// ---------------------------------------------------------------------------
__global__ void __launch_bounds__(512) ode_kernel(
    const float* __restrict__ person, const int* __restrict__ home_id,
    const int* __restrict__ work_id, const float* __restrict__ ztab,
    const float* __restrict__ times,
    const float* __restrict__ Wi, const float* __restrict__ bi,
    const float* __restrict__ W11, const float* __restrict__ b11,
    const float* __restrict__ W12, const float* __restrict__ b12,
    const float* __restrict__ W21, const float* __restrict__ b21,
    const float* __restrict__ W22, const float* __restrict__ b22,
    const float* __restrict__ Wo, const float* __restrict__ bo)
{
    extern __shared__ float sm[];
    float* sX  = sm;             // 160*RP = 5760
    float* sZ  = sX + 5760;      // 64*RP = 2304
    float* sZt = sZ + 2304;      // 2304
    float* sKs = sZt + 2304;     // 2304
    float* sH  = sKs + 2304;     // 128*RP = 4608
    float* sH2 = sH + 4608;      // 4608
    float* sF  = sH2 + 4608;     // 2304
    float* sB  = sF + 2304;      // 704
    float* sT  = sB + 704;       // 48

    const int tid = threadIdx.x;
    const int b0 = blockIdx.x * 32;

    for (int idx = tid; idx < 32 * 160; idx += 512) {
        int r = idx / 160, j = idx % 160, b = b0 + r;
        float v;
        if (j < 32)      v = person[b * 32 + j];
        else if (j < 96) v = ztab[(size_t)work_id[b] * 64 + (j - 32)];
        else             v = ztab[(size_t)home_id[b] * 64 + (j - 96)];
        sX[j * RP + r] = v;
    }
    for (int idx = tid; idx < 2048; idx += 512) {
        int c = idx & 63, r = idx >> 6;
        sZ[c * RP + r] = g_predz[(size_t)(b0 + r) * (T_ * L_) + c];
    }
    if (tid < 128) {
        sB[tid]       = bi[tid];
        sB[128 + tid] = b11[tid];
        sB[256 + tid] = b12[tid];
        sB[384 + tid] = b21[tid];
        sB[512 + tid] = b22[tid];
        if (tid < 64) sB[640 + tid] = bo[tid];
        if (tid < 48) sT[tid] = times[tid];
    }
    __syncthreads();

    for (int s = 0; s < T_ - 1; s++) {
        float t0 = sT[s], t1 = sT[s + 1];
        float dt = t1 - t0;

        ode_f(tid, t0, sX, sZ, sH, sH2, sF, sB, Wi, W11, W12, W21, W22, Wo);
        for (int idx = tid; idx < 2048; idx += 512) {
            int c = idx & 63, r = idx >> 6; int off = c * RP + r;
            float k1 = sF[off];
            sKs[off] = k1;
            sZt[off] = sZ[off] + 0.5f * dt * k1;
        }
        __syncthreads();

        ode_f(tid, t0 + 0.5f * dt, sX, sZt, sH, sH2, sF, sB, Wi, W11, W12, W21, W22, Wo);
        for (int idx = tid; idx < 2048; idx += 512) {
            int c = idx & 63, r = idx >> 6; int off = c * RP + r;
            float k2 = sF[off];
            sKs[off] += 2.0f * k2;
            sZt[off] = sZ[off] + 0.5f * dt * k2;
        }
        __syncthreads();

        ode_f(tid, t0 + 0.5f * dt, sX, sZt, sH, sH2, sF, sB, Wi, W11, W12, W21, W22, Wo);
        for (int idx = tid; idx < 2048; idx += 512) {
            int c = idx & 63, r = idx >> 6; int off = c * RP + r;
            float k3 = sF[off];
            sKs[off] += 2.0f * k3;
            sZt[off] = sZ[off] + dt * k3;
        }
        __syncthreads();

        ode_f(tid, t1, sX, sZt, sH, sH2, sF, sB, Wi, W11, W12, W21, W22, Wo);
        for (int idx = tid; idx < 2048; idx += 512) {
            int c = idx & 63, r = idx >> 6; int off = c * RP + r;
            float zn = sZ[off] + (dt * (1.0f / 6.0f)) * (sKs[off] + sF[off]);
            sZ[off] = zn;
            g_predz[(size_t)(b0 + r) * (T_ * L_) + (size_t)(s + 1) * L_ + c] = zn;
        }
        __syncthreads();
    }
}

// ---------------------------------------------------------------------------
// Decoder: unchanged (64-row x 128-col tiles, transposed PZ).
// ---------------------------------------------------------------------------
#define RPD 68   // 64 rows + 4 pad
__global__ void __launch_bounds__(256) dec_kernel(
    const float* __restrict__ dW, const float* __restrict__ db,
    float* __restrict__ out)
{
    __shared__ float PZ[64 * RPD];    // [64 cols][RPD rows]
    const int tid = threadIdx.x;
    const int w = tid >> 5, lane = tid & 31;
    const int ct = blockIdx.x;                 // 0..7
    const size_t row0 = (size_t)blockIdx.y * 64;

    for (int idx = tid; idx < 4096; idx += 256) {
        int c = idx & 63, r = idx >> 6;
        PZ[c * RPD + r] = g_predz[row0 * 64 + idx];
    }
    __syncthreads();

    const int cg = lane & 3, rg = lane >> 2;   // 4 cgs x 8 rgs
    const int c0 = ct * 128 + w * 16 + cg * 4;
    const int r0 = rg * 8;
    if (c0 >= Z_) return;

    u64 acc[4][4];
#pragma unroll
    for (int j = 0; j < 4; j++) {
        u64 ib = pk2(db[c0 + j], db[c0 + j]);
#pragma unroll
        for (int p = 0; p < 4; p++) acc[p][j] = ib;
    }
#pragma unroll 4
    for (int k = 0; k < 64; k++) {
        ulonglong2 a01 = *(const ulonglong2*)(PZ + k * RPD + r0);
        ulonglong2 a23 = *(const ulonglong2*)(PZ + k * RPD + r0 + 4);
        float4 wv = *(const float4*)(dW + (size_t)k * Z_ + c0);
        u64 wd[4];
        wd[0] = pk2(wv.x, wv.x); wd[1] = pk2(wv.y, wv.y);
        wd[2] = pk2(wv.z, wv.z); wd[3] = pk2(wv.w, wv.w);
        u64 ap[4] = { a01.x, a01.y, a23.x, a23.y };
#pragma unroll
        for (int p = 0; p < 4; p++)
#pragma unroll
            for (int j = 0; j < 4; j++)
                acc[p][j] = f2(ap[p], wd[j], acc[p][j]);
    }
#pragma unroll
    for (int p = 0; p < 4; p++) {
        float2 e0 = up2(acc[p][0]), e1 = up2(acc[p][1]);
        float2 e2 = up2(acc[p][2]), e3 = up2(acc[p][3]);
        float4 lo; lo.x = e0.x; lo.y = e1.x; lo.z = e2.x; lo.w = e3.x;
        float4 hi; hi.x = e0.y; hi.y = e1.y; hi.z = e2.y; hi.w = e3.y;
        *(float4*)&out[(row0 + r0 + 2 * p)     * Z_ + c0] = lo;
        *(float4*)&out[(row0 + r0 + 2 * p + 1) * Z_ + c0] = hi;
    }
}

// ---------------------------------------------------------------------------
extern "C" void kernel_launch(void* const* d_in, const int* in_sizes, int n_in,
                              void* d_out, int out_size)
{
    const float* person  = (const float*)d_in[0];
    const int*   home_id = (const int*)  d_in[1];
    const int*   work_id = (const int*)  d_in[2];
    const float* purpose = (const float*)d_in[3];
    const float* times   = (const float*)d_in[4];
    const float* eps     = (const float*)d_in[5];
    const float* ztab    = (const float*)d_in[6];
    const float* eW1     = (const float*)d_in[7];
    const float* eb1     = (const float*)d_in[8];
    const float* eW2     = (const float*)d_in[9];
    const float* eb2     = (const float*)d_in[10];
    const float* dW      = (const float*)d_in[11];
    const float* db      = (const float*)d_in[12];
    const float* Wi      = (const float*)d_in[13];
    const float* bi      = (const float*)d_in[14];
    const float* W11     = (const float*)d_in[15];
    const float* b11     = (const float*)d_in[16];
    const float* W12     = (const float*)d_in[17];
    const float* b12     = (const float*)d_in[18];
    const float* W21     = (const float*)d_in[19];
    const float* b21     = (const float*)d_in[20];
    const float* W22     = (const float*)d_in[21];
    const float* b22     = (const float*)d_in[22];
    const float* Wo      = (const float*)d_in[23];
    const float* bo      = (const float*)d_in[24];

    float* out_logits = (float*)d_out;                          // [B, T, Z]
    float* out_mu     = out_logits + (size_t)B_ * T_ * Z_;      // [B, L]
    float* out_lv     = out_mu + (size_t)B_ * L_;               // [B, L]

    enc_kernel<<<B_ / 16, 256>>>(person, home_id, work_id, purpose, eps, ztab,
                                 eW1, eb1, eW2, eb2, out_mu, out_lv);

    const int ODE_SMEM = (5760 + 2304 * 3 + 4608 * 2 + 2304 + 704 + 48) * 4; // 99776 B
    cudaFuncSetAttribute(ode_kernel, cudaFuncAttributeMaxDynamicSharedMemorySize, ODE_SMEM);
    ode_kernel<<<B_ / 32, 512, ODE_SMEM>>>(person, home_id, work_id, ztab, times,
                                           Wi, bi, W11, b11, W12, b12,
                                           W21, b21, W22, b22, Wo, bo);

    dim3 dgrid(8, (B_ * T_) / 64);
    dec_kernel<<<dgrid, 256>>>(dW, db, out_logits);
}